// round 1
// baseline (speedup 1.0000x reference)
#include <cuda_runtime.h>

#define HID     1024
#define TSTEPS  4096
#define NCTA    128
#define NTHREADS 256   // 8 warps; warp w of CTA b owns hidden index j = b*8+w for both layers

__device__ float g_h1[2][HID];
__device__ float g_h2[2][HID];
__device__ unsigned g_cnt = 0;
__device__ unsigned g_gen = 0;

__device__ __forceinline__ float warpsum(float v) {
#pragma unroll
    for (int s = 16; s; s >>= 1) v += __shfl_xor_sync(0xffffffffu, v, s);
    return v;
}

__device__ __forceinline__ void gridbar() {
    __syncthreads();
    if (threadIdx.x == 0) {
        __threadfence();
        unsigned g = *((volatile unsigned*)&g_gen);
        if (atomicAdd(&g_cnt, 1u) == NCTA - 1) {
            atomicExch(&g_cnt, 0u);
            __threadfence();
            atomicExch(&g_gen, g + 1u);
        } else {
            while (*((volatile unsigned*)&g_gen) == g) { }
        }
    }
    __syncthreads();
}

__device__ __forceinline__ float sigf(float x) { return 1.0f / (1.0f + __expf(-x)); }

__device__ __forceinline__ float dot4(float4 a, float4 b) {
    return fmaf(a.x, b.x, fmaf(a.y, b.y, fmaf(a.z, b.z, a.w * b.w)));
}

__global__ void __launch_bounds__(NTHREADS, 1)
lstm_persistent(const float* __restrict__ x,
                const float* __restrict__ Wih1, const float* __restrict__ Whh1,
                const float* __restrict__ bih1, const float* __restrict__ bhh1,
                const float* __restrict__ Wih2, const float* __restrict__ Whh2,
                const float* __restrict__ bih2, const float* __restrict__ bhh2,
                const float* __restrict__ Wout, const float* __restrict__ bout,
                float* __restrict__ out)
{
    const int warp = threadIdx.x >> 5;
    const int lane = threadIdx.x & 31;
    const int b    = blockIdx.x;
    const int j    = b * 8 + warp;   // owned hidden index (layer1 and layer2)

    // ---- per-run init: zero parity-0 h buffers (parity-1 written before read) ----
    if (threadIdx.x < 8) {
        int j0 = b * 8 + threadIdx.x;
        __stcg(&g_h1[0][j0], 0.0f);
        __stcg(&g_h2[0][j0], 0.0f);
    }

    // bias sums per gate (uniform per warp; broadcast loads)
    float bs1[4], bs2[4];
#pragma unroll
    for (int g = 0; g < 4; ++g) {
        bs1[g] = __ldg(&bih1[g * HID + j]) + __ldg(&bhh1[g * HID + j]);
        bs2[g] = __ldg(&bih2[g * HID + j]) + __ldg(&bhh2[g * HID + j]);
    }
    const float bout_w = (warp < 2) ? __ldg(&bout[warp]) : 0.0f;

    float c1 = 0.0f, c2 = 0.0f;
    float pg2[4];  // stashed partial layer-2 gates (Whh2 @ h2_prev + biases)

    gridbar();  // zeros visible everywhere

    for (int t = 0; t < TSTEPS; ++t) {
        const float4* h1p4 = (const float4*)g_h1[t & 1];
        const float4* h2p4 = (const float4*)g_h2[t & 1];
        float* h1n = g_h1[(t + 1) & 1];
        float* h2n = g_h2[(t + 1) & 1];

        // cache prev hidden vectors in registers (L2-coherent loads)
        float4 h1r[8], h2r[8];
#pragma unroll
        for (int k = 0; k < 8; ++k) {
            h1r[k] = __ldcg(h1p4 + lane + k * 32);
            h2r[k] = __ldcg(h2p4 + lane + k * 32);
        }

        float4 xr = make_float4(0.f, 0.f, 0.f, 0.f);
        if (lane < 16) xr = __ldg((const float4*)(x + t * 64) + lane);

        // ---- stage 1: layer-1 gates + partial layer-2 gates (Whh2 @ h2_prev) ----
        float acc1[4], acc2[4];
#pragma unroll
        for (int g = 0; g < 4; ++g) {
            const float4* row1 = (const float4*)(Whh1 + (size_t)(g * HID + j) * HID);
            const float4* row2 = (const float4*)(Whh2 + (size_t)(g * HID + j) * HID);
            float a1 = 0.f, a2 = 0.f;
#pragma unroll
            for (int k = 0; k < 8; ++k) {
                a1 += dot4(__ldg(row1 + lane + k * 32), h1r[k]);
                a2 += dot4(__ldg(row2 + lane + k * 32), h2r[k]);
            }
            if (lane < 16) {
                float4 wx = __ldg((const float4*)(Wih1 + (size_t)(g * HID + j) * 64) + lane);
                a1 += dot4(wx, xr);
            }
            acc1[g] = a1;
            acc2[g] = a2;
        }
#pragma unroll
        for (int g = 0; g < 4; ++g) {
            acc1[g] = warpsum(acc1[g]) + bs1[g];
            pg2[g]  = warpsum(acc2[g]) + bs2[g];
        }

        {   // layer-1 cell update (all lanes compute; lane 0 publishes)
            float ig = sigf(acc1[0]);
            float fg = sigf(acc1[1]);
            float gg = tanhf(acc1[2]);
            float og = sigf(acc1[3]);
            c1 = fg * c1 + ig * gg;
            float h1v = og * tanhf(c1);
            if (lane == 0) __stcg(&h1n[j], h1v);
        }

        // output projection for out[t-1] (reuses h2r = h2_prev), done by CTA0 warps 0,1
        if (b == 0 && warp < 2 && t > 0) {
            const float4* rw = (const float4*)(Wout + warp * HID);
            float a = 0.f;
#pragma unroll
            for (int k = 0; k < 8; ++k) a += dot4(__ldg(rw + lane + k * 32), h2r[k]);
            a = warpsum(a);
            if (lane == 0) out[(t - 1) * 2 + warp] = a + bout_w;
        }

        gridbar();  // publish h1_new

        // ---- stage 2: Wih2 @ h1_new, finish layer-2 ----
        float4 h1nr[8];
#pragma unroll
        for (int k = 0; k < 8; ++k) h1nr[k] = __ldcg((const float4*)h1n + lane + k * 32);

        float acc3[4];
#pragma unroll
        for (int g = 0; g < 4; ++g) {
            const float4* row = (const float4*)(Wih2 + (size_t)(g * HID + j) * HID);
            float a = 0.f;
#pragma unroll
            for (int k = 0; k < 8; ++k) a += dot4(__ldg(row + lane + k * 32), h1nr[k]);
            acc3[g] = a;
        }
#pragma unroll
        for (int g = 0; g < 4; ++g) acc3[g] = warpsum(acc3[g]) + pg2[g];

        {
            float ig = sigf(acc3[0]);
            float fg = sigf(acc3[1]);
            float gg = tanhf(acc3[2]);
            float og = sigf(acc3[3]);
            c2 = fg * c2 + ig * gg;
            float h2v = og * tanhf(c2);
            if (lane == 0) __stcg(&h2n[j], h2v);
        }

        gridbar();  // publish h2_new
    }

    // final output row out[T-1] (h2 final lives in parity (TSTEPS & 1) == 0)
    if (b == 0 && warp < 2) {
        const float4* h2f = (const float4*)g_h2[TSTEPS & 1];
        const float4* rw  = (const float4*)(Wout + warp * HID);
        float a = 0.f;
#pragma unroll
        for (int k = 0; k < 8; ++k) a += dot4(__ldg(rw + lane + k * 32), __ldcg(h2f + lane + k * 32));
        a = warpsum(a);
        if (lane == 0) out[(TSTEPS - 1) * 2 + warp] = a + bout_w;
    }
}

extern "C" void kernel_launch(void* const* d_in, const int* in_sizes, int n_in,
                              void* d_out, int out_size)
{
    const float* x    = (const float*)d_in[0];
    const float* Wih1 = (const float*)d_in[1];
    const float* Whh1 = (const float*)d_in[2];
    const float* bih1 = (const float*)d_in[3];
    const float* bhh1 = (const float*)d_in[4];
    const float* Wih2 = (const float*)d_in[5];
    const float* Whh2 = (const float*)d_in[6];
    const float* bih2 = (const float*)d_in[7];
    const float* bhh2 = (const float*)d_in[8];
    const float* Wout = (const float*)d_in[9];
    const float* bout = (const float*)d_in[10];
    float* out = (float*)d_out;

    lstm_persistent<<<NCTA, NTHREADS>>>(x, Wih1, Whh1, bih1, bhh1,
                                        Wih2, Whh2, bih2, bhh2, Wout, bout, out);
}

// round 2
// speedup vs baseline: 1.2410x; 1.2410x over previous
#include <cuda_runtime.h>
#include <cuda_fp16.h>

#define HID      1024
#define TSTEPS   4096
#define NCTA     128
#define NTHREADS 512   // 16 warps: warp w -> j_local = w>>1, K-half = w&1

// SMEM: 3 weight mats fp16 (3*32*1024*2 = 196608 B) + 2*64 part floats (512 B)
//       + 2 h vectors fp16 (2*2048 B)  => 201216 B
#define SMEM_BYTES 201216

__device__ float    g_h1v[HID];
__device__ float    g_h2v[HID];
__device__ unsigned g_cnt = 0;
__device__ unsigned g_gen = 0;

__device__ __forceinline__ float warpsum(float v) {
#pragma unroll
    for (int s = 16; s; s >>= 1) v += __shfl_xor_sync(0xffffffffu, v, s);
    return v;
}

__device__ __forceinline__ void gridbar() {
    __syncthreads();
    if (threadIdx.x == 0) {
        __threadfence();
        unsigned g = *((volatile unsigned*)&g_gen);
        if (atomicAdd(&g_cnt, 1u) == NCTA - 1) {
            atomicExch(&g_cnt, 0u);
            __threadfence();
            atomicExch(&g_gen, g + 1u);
        } else {
            while (*((volatile unsigned*)&g_gen) == g) { }
        }
    }
    __syncthreads();
}

__device__ __forceinline__ float sigf(float x) { return 1.0f / (1.0f + __expf(-x)); }

__device__ __forceinline__ float dot4(float4 a, float4 b) {
    return fmaf(a.x, b.x, fmaf(a.y, b.y, fmaf(a.z, b.z, a.w * b.w)));
}

// unpack 8 halfs (one uint4) into 8 floats
__device__ __forceinline__ void unp8(uint4 u, float* f) {
    float2 t;
    t = __half22float2(*reinterpret_cast<__half2*>(&u.x)); f[0] = t.x; f[1] = t.y;
    t = __half22float2(*reinterpret_cast<__half2*>(&u.y)); f[2] = t.x; f[3] = t.y;
    t = __half22float2(*reinterpret_cast<__half2*>(&u.z)); f[4] = t.x; f[5] = t.y;
    t = __half22float2(*reinterpret_cast<__half2*>(&u.w)); f[6] = t.x; f[7] = t.y;
}

__global__ void __launch_bounds__(NTHREADS, 1)
lstm_persistent(const float* __restrict__ x,
                const float* __restrict__ Wih1, const float* __restrict__ Whh1,
                const float* __restrict__ bih1, const float* __restrict__ bhh1,
                const float* __restrict__ Wih2, const float* __restrict__ Whh2,
                const float* __restrict__ bih2, const float* __restrict__ bhh2,
                const float* __restrict__ Wout, const float* __restrict__ bout,
                float* __restrict__ out)
{
    extern __shared__ unsigned char smraw[];
    __half* sWhh1 = (__half*)smraw;            // [8][4][1024]
    __half* sWhh2 = sWhh1 + 32768;
    __half* sWih2 = sWhh2 + 32768;
    float*  sPart1 = (float*)(sWih2 + 32768);  // [8][4][2]
    float*  sPart2 = sPart1 + 64;
    __half* sH1n  = (__half*)(sPart2 + 64);    // h1(t)   staged, fp16
    __half* sH2p  = sH1n + HID;                // h2(t-1) staged, fp16

    const int tid  = threadIdx.x;
    const int w    = tid >> 5;
    const int lane = tid & 31;
    const int j    = w >> 1;      // local hidden index 0..7
    const int kh   = w & 1;       // K half
    const int b    = blockIdx.x;
    const int jg   = b * 8 + j;   // global hidden index

    // ---- preload weights fp32 -> fp16 SMEM (one-time, ~10us) ----
    {
        const float* srcs[3] = { Whh1, Whh2, Wih2 };
        __half* dsts[3] = { sWhh1, sWhh2, sWih2 };
        for (int r = w; r < 32; r += 16) {          // 2 rows per warp
            int rj = r >> 2, rg = r & 3;
            size_t so = ((size_t)rg * HID + (size_t)(b * 8 + rj)) * HID;
#pragma unroll
            for (int m = 0; m < 3; ++m) {
                const float4* src = (const float4*)(srcs[m] + so);
                __half* dst = dsts[m] + (rj * 4 + rg) * HID;
#pragma unroll
                for (int i = 0; i < 8; ++i) {
                    float4 v = __ldg(src + lane + 32 * i);
                    __half2* d = (__half2*)dst + (lane + 32 * i) * 2;
                    d[0] = __floats2half2_rn(v.x, v.y);
                    d[1] = __floats2half2_rn(v.z, v.w);
                }
            }
        }
    }
    if (tid < 128) ((uint4*)sH2p)[tid] = make_uint4(0, 0, 0, 0);

    // bias sums (only lane0 of kh==0 warps actually uses them)
    float bs1[4], bs2[4];
#pragma unroll
    for (int g = 0; g < 4; ++g) {
        bs1[g] = __ldg(&bih1[g * HID + jg]) + __ldg(&bhh1[g * HID + jg]);
        bs2[g] = __ldg(&bih2[g * HID + jg]) + __ldg(&bhh2[g * HID + jg]);
    }

    // stash1 = (un-reduced) Whh1 @ h1(t-1) + Wih1 @ x(t); init for t=0 (h1=0)
    float stash1[4] = {0.f, 0.f, 0.f, 0.f};
    if (kh == 0 && lane < 16) {
        float4 xv = __ldg((const float4*)x + lane);
#pragma unroll
        for (int g = 0; g < 4; ++g) {
            float4 wv = __ldg((const float4*)(Wih1 + (size_t)(g * HID + jg) * 64) + lane);
            stash1[g] = dot4(wv, xv);
        }
    }
    float c1 = 0.f, c2 = 0.f;

    // output-projection warps (CTA0 only): w13 -> out col 0, w15 -> out col 1
    const bool outw = (b == 0) && (w == 13 || w == 15);
    const int  oidx = (w == 15) ? 1 : 0;
    const float bo  = outw ? __ldg(&bout[oidx]) : 0.f;
    const float* worow = Wout + oidx * HID;

    __syncthreads();

    const int i0 = kh * 64 + lane;
    const int i1 = i0 + 32;

    for (int t = 0; t < TSTEPS; ++t) {
        // ---- out[t-1] = Wout @ h2(t-1) (sH2p) ----
        if (outw && t > 0) {
            float a = 0.f;
#pragma unroll
            for (int i = 0; i < 8; ++i) {
                float4 wv = __ldg((const float4*)worow + lane + 32 * i);
                const __half2* hp = (const __half2*)sH2p + (lane + 32 * i) * 2;
                float2 h01 = __half22float2(hp[0]);
                float2 h23 = __half22float2(hp[1]);
                a = fmaf(wv.x, h01.x, fmaf(wv.y, h01.y,
                    fmaf(wv.z, h23.x, fmaf(wv.w, h23.y, a))));
            }
            a = warpsum(a);
            if (lane == 0) out[(t - 1) * 2 + oidx] = a + bo;
        }

        // ---- A: acc2 = Whh2 @ h2(t-1) (layer-2 partial) ----
        float hb[16];
        unp8(((const uint4*)sH2p)[i0], hb);
        unp8(((const uint4*)sH2p)[i1], hb + 8);
        float acc2[4];
#pragma unroll
        for (int g = 0; g < 4; ++g) {
            const uint4* row = (const uint4*)(sWhh2 + (j * 4 + g) * HID);
            float wf[16];
            unp8(row[i0], wf); unp8(row[i1], wf + 8);
            float a = 0.f;
#pragma unroll
            for (int k = 0; k < 16; ++k) a = fmaf(wf[k], hb[k], a);
            acc2[g] = a;
        }

        // ---- B: reduce stash1 (layer-1 gates) ----
#pragma unroll
        for (int g = 0; g < 4; ++g) {
            float s = warpsum(stash1[g]);
            if (lane == 0) sPart1[(j * 4 + g) * 2 + kh] = s;
        }
        __syncthreads();

        // ---- C: finalize layer 1, publish h1(t) ----
        if (kh == 0 && lane == 0) {
            float gi = sPart1[(j * 4 + 0) * 2] + sPart1[(j * 4 + 0) * 2 + 1] + bs1[0];
            float gf = sPart1[(j * 4 + 1) * 2] + sPart1[(j * 4 + 1) * 2 + 1] + bs1[1];
            float gg = sPart1[(j * 4 + 2) * 2] + sPart1[(j * 4 + 2) * 2 + 1] + bs1[2];
            float go = sPart1[(j * 4 + 3) * 2] + sPart1[(j * 4 + 3) * 2 + 1] + bs1[3];
            float iv = sigf(gi), fv = sigf(gf), gv = tanhf(gg), ov = sigf(go);
            c1 = fv * c1 + iv * gv;
            float h1 = ov * tanhf(c1);
            __stcg(&g_h1v[jg], h1);
            __threadfence();
        }
        gridbar();  // B1: h1(t) visible everywhere

        // ---- E: stage h1(t) -> sH1n (fp16) ----
        if (tid < 256) {
            float4 v = __ldcg((const float4*)g_h1v + tid);
            __half2* d = (__half2*)sH1n + tid * 2;
            d[0] = __floats2half2_rn(v.x, v.y);
            d[1] = __floats2half2_rn(v.z, v.w);
        }
        __syncthreads();

        // ---- F: layer-2 gates = Wih2 @ h1(t) + acc2; finalize h2(t) ----
        float hn[16];
        unp8(((const uint4*)sH1n)[i0], hn);
        unp8(((const uint4*)sH1n)[i1], hn + 8);
#pragma unroll
        for (int g = 0; g < 4; ++g) {
            const uint4* row = (const uint4*)(sWih2 + (j * 4 + g) * HID);
            float wf[16];
            unp8(row[i0], wf); unp8(row[i1], wf + 8);
            float a = acc2[g];
#pragma unroll
            for (int k = 0; k < 16; ++k) a = fmaf(wf[k], hn[k], a);
            a = warpsum(a);
            if (lane == 0) sPart2[(j * 4 + g) * 2 + kh] = a;
        }
        __syncthreads();
        if (kh == 0 && lane == 0) {
            float gi = sPart2[(j * 4 + 0) * 2] + sPart2[(j * 4 + 0) * 2 + 1] + bs2[0];
            float gf = sPart2[(j * 4 + 1) * 2] + sPart2[(j * 4 + 1) * 2 + 1] + bs2[1];
            float gg = sPart2[(j * 4 + 2) * 2] + sPart2[(j * 4 + 2) * 2 + 1] + bs2[2];
            float go = sPart2[(j * 4 + 3) * 2] + sPart2[(j * 4 + 3) * 2 + 1] + bs2[3];
            float iv = sigf(gi), fv = sigf(gf), gv = tanhf(gg), ov = sigf(go);
            c2 = fv * c2 + iv * gv;
            float h2 = ov * tanhf(c2);
            __stcg(&g_h2v[jg], h2);
            __threadfence();
        }

        // ---- G (barrier shadow): stash1 for t+1 = Whh1 @ h1(t) + Wih1 @ x(t+1) ----
#pragma unroll
        for (int g = 0; g < 4; ++g) {
            const uint4* row = (const uint4*)(sWhh1 + (j * 4 + g) * HID);
            float wf[16];
            unp8(row[i0], wf); unp8(row[i1], wf + 8);
            float a = 0.f;
#pragma unroll
            for (int k = 0; k < 16; ++k) a = fmaf(wf[k], hn[k], a);
            stash1[g] = a;
        }
        if (kh == 0 && lane < 16 && t + 1 < TSTEPS) {
            float4 xv = __ldg((const float4*)(x + (size_t)(t + 1) * 64) + lane);
#pragma unroll
            for (int g = 0; g < 4; ++g) {
                float4 wv = __ldg((const float4*)(Wih1 + (size_t)(g * HID + jg) * 64) + lane);
                stash1[g] = fmaf(wv.x, xv.x, fmaf(wv.y, xv.y,
                            fmaf(wv.z, xv.z, fmaf(wv.w, xv.w, stash1[g]))));
            }
        }
        gridbar();  // B2: h2(t) visible everywhere

        // ---- I: stage h2(t) -> sH2p ----
        if (tid < 256) {
            float4 v = __ldcg((const float4*)g_h2v + tid);
            __half2* d = (__half2*)sH2p + tid * 2;
            d[0] = __floats2half2_rn(v.x, v.y);
            d[1] = __floats2half2_rn(v.z, v.w);
        }
        __syncthreads();
    }

    // ---- final output row out[T-1] from sH2p = h2(T-1) ----
    if (outw) {
        float a = 0.f;
#pragma unroll
        for (int i = 0; i < 8; ++i) {
            float4 wv = __ldg((const float4*)worow + lane + 32 * i);
            const __half2* hp = (const __half2*)sH2p + (lane + 32 * i) * 2;
            float2 h01 = __half22float2(hp[0]);
            float2 h23 = __half22float2(hp[1]);
            a = fmaf(wv.x, h01.x, fmaf(wv.y, h01.y,
                fmaf(wv.z, h23.x, fmaf(wv.w, h23.y, a))));
        }
        a = warpsum(a);
        if (lane == 0) out[(TSTEPS - 1) * 2 + oidx] = a + bo;
    }
}

extern "C" void kernel_launch(void* const* d_in, const int* in_sizes, int n_in,
                              void* d_out, int out_size)
{
    const float* x    = (const float*)d_in[0];
    const float* Wih1 = (const float*)d_in[1];
    const float* Whh1 = (const float*)d_in[2];
    const float* bih1 = (const float*)d_in[3];
    const float* bhh1 = (const float*)d_in[4];
    const float* Wih2 = (const float*)d_in[5];
    const float* Whh2 = (const float*)d_in[6];
    const float* bih2 = (const float*)d_in[7];
    const float* bhh2 = (const float*)d_in[8];
    const float* Wout = (const float*)d_in[9];
    const float* bout = (const float*)d_in[10];
    float* out = (float*)d_out;

    cudaFuncSetAttribute(lstm_persistent,
                         cudaFuncAttributeMaxDynamicSharedMemorySize, SMEM_BYTES);

    lstm_persistent<<<NCTA, NTHREADS, SMEM_BYTES>>>(x, Wih1, Whh1, bih1, bhh1,
                                                    Wih2, Whh2, bih2, bhh2,
                                                    Wout, bout, out);
}

// round 3
// speedup vs baseline: 2.1891x; 1.7639x over previous
#include <cuda_runtime.h>
#include <cuda_fp16.h>

#define HID     1024
#define TSTEPS  4096
#define NCTA    128
#define NTH     512   // 16 warps; warp w owns gate-rows {2w,2w+1} of layer1 AND layer2

// SMEM: Whh1/Wih2/Whh2 fp16 (3*64KB) + Wih1 (4KB) + sH1/sH2 (2*2KB) + gates (256B)
#define SMEM_BYTES (3*65536 + 4096 + 2*2048 + 256)

__device__ __align__(16) __half g_h1[2][HID];
__device__ __align__(16) __half g_h2[2][HID];
__device__ unsigned g_cnt = 0;
__device__ unsigned g_gen = 0;

__device__ __forceinline__ float warpsum(float v) {
#pragma unroll
    for (int s = 16; s; s >>= 1) v += __shfl_xor_sync(0xffffffffu, v, s);
    return v;
}

__device__ __forceinline__ void gridbar() {
    __syncthreads();
    if (threadIdx.x == 0) {
        __threadfence();
        unsigned g = *((volatile unsigned*)&g_gen);
        if (atomicAdd(&g_cnt, 1u) == NCTA - 1) {
            atomicExch(&g_cnt, 0u);
            __threadfence();
            atomicExch(&g_gen, g + 1u);
        } else {
            while (*((volatile unsigned*)&g_gen) == g) { }
        }
    }
    __syncthreads();
}

__device__ __forceinline__ float sigf(float x) {
    return __fdividef(1.0f, 1.0f + __expf(-x));
}
__device__ __forceinline__ float tanhfast(float x) {
    return 2.0f * __fdividef(1.0f, 1.0f + __expf(-2.0f * x)) - 1.0f;
}

__device__ __forceinline__ void unp8(uint4 u, float* f) {
    float2 t;
    t = __half22float2(*reinterpret_cast<__half2*>(&u.x)); f[0] = t.x; f[1] = t.y;
    t = __half22float2(*reinterpret_cast<__half2*>(&u.y)); f[2] = t.x; f[3] = t.y;
    t = __half22float2(*reinterpret_cast<__half2*>(&u.z)); f[4] = t.x; f[5] = t.y;
    t = __half22float2(*reinterpret_cast<__half2*>(&u.w)); f[6] = t.x; f[7] = t.y;
}

__global__ void __launch_bounds__(NTH, 1)
lstm_persistent(const float* __restrict__ x,
                const float* __restrict__ Wih1, const float* __restrict__ Whh1,
                const float* __restrict__ bih1, const float* __restrict__ bhh1,
                const float* __restrict__ Wih2, const float* __restrict__ Whh2,
                const float* __restrict__ bih2, const float* __restrict__ bhh2,
                const float* __restrict__ Wout, const float* __restrict__ bout,
                float* __restrict__ out)
{
    extern __shared__ unsigned char sm[];
    __half* sWhh1 = (__half*)sm;                 // [32][1024]
    __half* sWih2 = sWhh1 + 32 * HID;
    __half* sWhh2 = sWih2 + 32 * HID;
    __half* sWih1 = sWhh2 + 32 * HID;            // [32][64]
    __half* sH1   = sWih1 + 32 * 64;             // h1(t)   fp16
    __half* sH2   = sH1 + HID;                   // h2(t-1) fp16
    float*  sG1   = (float*)(sH2 + HID);         // 32 gate-row sums, layer1
    float*  sG2   = sG1 + 32;                    // 32 gate-row sums, layer2

    const int tid  = threadIdx.x;
    const int w    = tid >> 5;
    const int lane = tid & 31;
    const int b    = blockIdx.x;
    const int r0   = 2 * w;
    const int r1   = 2 * w + 1;

    // ---- preload: 3 big mats -> fp16 SMEM (rows 4j+g owned by this CTA) ----
    {
        const float* srcs[3] = { Whh1, Wih2, Whh2 };
        __half* dsts[3] = { sWhh1, sWih2, sWhh2 };
        for (int rr = w; rr < 96; rr += 16) {
            int m = rr >> 5, r = rr & 31;
            int g = r & 3, jg = 8 * b + (r >> 2);
            const float4* src = (const float4*)(srcs[m] + ((size_t)g * HID + jg) * HID);
            uint4* dst = (uint4*)(dsts[m] + r * HID);
#pragma unroll
            for (int i = 0; i < 4; ++i) {
                int k = lane + 32 * i;
                float4 a  = __ldg(src + 2 * k);
                float4 bb = __ldg(src + 2 * k + 1);
                uint4 u;
                ((__half2*)&u)[0] = __floats2half2_rn(a.x, a.y);
                ((__half2*)&u)[1] = __floats2half2_rn(a.z, a.w);
                ((__half2*)&u)[2] = __floats2half2_rn(bb.x, bb.y);
                ((__half2*)&u)[3] = __floats2half2_rn(bb.z, bb.w);
                dst[k] = u;
            }
        }
    }
    // ---- preload Wih1 rows r0,r1 ----
#pragma unroll
    for (int rl = 0; rl < 2; ++rl) {
        int r = 2 * w + rl;
        int g = r & 3, jg = 8 * b + (r >> 2);
        if (lane < 16) {
            float4 v = __ldg((const float4*)(Wih1 + ((size_t)g * HID + jg) * 64) + lane);
            __half2* d = (__half2*)(sWih1 + r * 64) + 2 * lane;
            d[0] = __floats2half2_rn(v.x, v.y);
            d[1] = __floats2half2_rn(v.z, v.w);
        }
    }
    // h2(-1) = 0 lives at parity 1
    if (tid < 8) g_h2[1][8 * b + tid] = __float2half(0.0f);

    // ---- finisher role: lane0 of warp w finishes (layer fl, j fj) ----
    const int fl = w >> 3, fj = w & 7, fjg = 8 * b + fj;
    float bsum[4] = {0.f, 0.f, 0.f, 0.f};
    if (lane == 0) {
        const float* bi = fl ? bih2 : bih1;
        const float* bh = fl ? bhh2 : bhh1;
#pragma unroll
        for (int g = 0; g < 4; ++g)
            bsum[g] = __ldg(bi + g * HID + fjg) + __ldg(bh + g * HID + fjg);
    }
    float cstate = 0.0f;

    // ---- output-projection role (warp 15 of CTA 1 -> col0, CTA 65 -> col1) ----
    const bool outw = (w == 15) && (b == 1 || b == 65);
    const int  oi   = (b == 65) ? 1 : 0;
    float bo = 0.0f;
    if (outw && lane == 0) bo = __ldg(bout + oi);
    const float4* worow = (const float4*)(Wout + oi * HID);

    __syncthreads();

    // ---- prologue: h1(0) = gates(Wih1 @ x(0) + biases), h_prev = 0 ----
    {
        float2 xv = __ldg((const float2*)x + lane);
        float2 w0 = __half22float2(((const __half2*)(sWih1 + r0 * 64))[lane]);
        float2 w1 = __half22float2(((const __half2*)(sWih1 + r1 * 64))[lane]);
        float a0 = warpsum(fmaf(w0.x, xv.x, w0.y * xv.y));
        float a1 = warpsum(fmaf(w1.x, xv.x, w1.y * xv.y));
        if (lane == 0) { sG1[r0] = a0; sG1[r1] = a1; }
        __syncthreads();
        if (lane == 0 && fl == 0) {
            float gi = sG1[fj * 4 + 0] + bsum[0];
            float gg = sG1[fj * 4 + 2] + bsum[2];
            float go = sG1[fj * 4 + 3] + bsum[3];
            cstate = sigf(gi) * tanhfast(gg);        // f*0 + i*g
            float h = sigf(go) * tanhfast(cstate);
            g_h1[0][fjg] = __float2half(h);
            __threadfence();
        }
    }
    gridbar();

    // ==== main loop: between barriers compute h2(t) AND h1(t+1) ====
    for (int t = 0; t < TSTEPS; ++t) {
        const int p1 = t & 1;        // parity of h1(t) and of h2(t) write
        const int p2 = p1 ^ 1;       // parity of h2(t-1) and of h1(t+1) write

        // stage published fp16 h vectors into SMEM (raw copy)
        if (tid < 128)
            ((uint4*)sH1)[tid] = __ldcg((const uint4*)g_h1[p1] + tid);
        else if (tid < 256)
            ((uint4*)sH2)[tid - 128] = __ldcg((const uint4*)g_h2[p2] + (tid - 128));
        __syncthreads();

        // out[t-1] = Wout @ h2(t-1)
        if (outw && t > 0) {
            float a = 0.f;
#pragma unroll
            for (int c = 0; c < 4; ++c) {
                int k = lane + 32 * c;
                float hf[8]; unp8(((const uint4*)sH2)[k], hf);
                float4 wa = __ldg(worow + 2 * k);
                float4 wb = __ldg(worow + 2 * k + 1);
                a = fmaf(wa.x, hf[0], fmaf(wa.y, hf[1], fmaf(wa.z, hf[2], fmaf(wa.w, hf[3], a))));
                a = fmaf(wb.x, hf[4], fmaf(wb.y, hf[5], fmaf(wb.z, hf[6], fmaf(wb.w, hf[7], a))));
            }
            a = warpsum(a);
            if (lane == 0) out[(t - 1) * 2 + oi] = a + bo;
        }

        // ---- dots: a1* = Whh1@h1(t) rows r0,r1 ; a2* = Wih2@h1(t)+Whh2@h2(t-1) ----
        float a1x = 0.f, a1y = 0.f, a2x = 0.f, a2y = 0.f;
        const uint4* W11a = (const uint4*)(sWhh1 + r0 * HID);
        const uint4* W11b = (const uint4*)(sWhh1 + r1 * HID);
        const uint4* Wi2a = (const uint4*)(sWih2 + r0 * HID);
        const uint4* Wi2b = (const uint4*)(sWih2 + r1 * HID);
        const uint4* Wh2a = (const uint4*)(sWhh2 + r0 * HID);
        const uint4* Wh2b = (const uint4*)(sWhh2 + r1 * HID);
#pragma unroll
        for (int c = 0; c < 4; ++c) {
            int k = lane + 32 * c;
            float h1f[8], h2f[8], wf[8];
            unp8(((const uint4*)sH1)[k], h1f);
            unp8(((const uint4*)sH2)[k], h2f);
            unp8(W11a[k], wf);
#pragma unroll
            for (int e = 0; e < 8; ++e) a1x = fmaf(wf[e], h1f[e], a1x);
            unp8(W11b[k], wf);
#pragma unroll
            for (int e = 0; e < 8; ++e) a1y = fmaf(wf[e], h1f[e], a1y);
            unp8(Wi2a[k], wf);
#pragma unroll
            for (int e = 0; e < 8; ++e) a2x = fmaf(wf[e], h1f[e], a2x);
            unp8(Wi2b[k], wf);
#pragma unroll
            for (int e = 0; e < 8; ++e) a2y = fmaf(wf[e], h1f[e], a2y);
            unp8(Wh2a[k], wf);
#pragma unroll
            for (int e = 0; e < 8; ++e) a2x = fmaf(wf[e], h2f[e], a2x);
            unp8(Wh2b[k], wf);
#pragma unroll
            for (int e = 0; e < 8; ++e) a2y = fmaf(wf[e], h2f[e], a2y);
        }
        // + Wih1 @ x(t+1) into layer-1 rows
        {
            float2 xv = make_float2(0.f, 0.f);
            if (t + 1 < TSTEPS)
                xv = __ldg((const float2*)(x + (size_t)(t + 1) * 64) + lane);
            float2 w0 = __half22float2(((const __half2*)(sWih1 + r0 * 64))[lane]);
            float2 w1 = __half22float2(((const __half2*)(sWih1 + r1 * 64))[lane]);
            a1x = fmaf(w0.x, xv.x, fmaf(w0.y, xv.y, a1x));
            a1y = fmaf(w1.x, xv.x, fmaf(w1.y, xv.y, a1y));
        }

        a1x = warpsum(a1x); a1y = warpsum(a1y);
        a2x = warpsum(a2x); a2y = warpsum(a2y);
        if (lane == 0) { sG1[r0] = a1x; sG1[r1] = a1y; sG2[r0] = a2x; sG2[r1] = a2y; }
        __syncthreads();

        // ---- finish: lane0 of warp w updates (fl, fj), publishes fp16 h ----
        if (lane == 0) {
            const float* sG = fl ? sG2 : sG1;
            float gi = sG[fj * 4 + 0] + bsum[0];
            float gf = sG[fj * 4 + 1] + bsum[1];
            float gg = sG[fj * 4 + 2] + bsum[2];
            float go = sG[fj * 4 + 3] + bsum[3];
            cstate = sigf(gf) * cstate + sigf(gi) * tanhfast(gg);
            float h = sigf(go) * tanhfast(cstate);
            if (fl == 0) g_h1[p2][fjg] = __float2half(h);   // h1(t+1)
            else         g_h2[p1][fjg] = __float2half(h);   // h2(t)
            __threadfence();
        }
        gridbar();
    }

    // ---- final out[T-1] from h2(T-1) at parity (T-1)&1 = 1 ----
    if (outw) {
        float a = 0.f;
#pragma unroll
        for (int c = 0; c < 4; ++c) {
            int k = lane + 32 * c;
            float hf[8]; unp8(__ldcg((const uint4*)g_h2[1] + k), hf);
            float4 wa = __ldg(worow + 2 * k);
            float4 wb = __ldg(worow + 2 * k + 1);
            a = fmaf(wa.x, hf[0], fmaf(wa.y, hf[1], fmaf(wa.z, hf[2], fmaf(wa.w, hf[3], a))));
            a = fmaf(wb.x, hf[4], fmaf(wb.y, hf[5], fmaf(wb.z, hf[6], fmaf(wb.w, hf[7], a))));
        }
        a = warpsum(a);
        if (lane == 0) out[(TSTEPS - 1) * 2 + oi] = a + bo;
    }
}

extern "C" void kernel_launch(void* const* d_in, const int* in_sizes, int n_in,
                              void* d_out, int out_size)
{
    const float* x    = (const float*)d_in[0];
    const float* Wih1 = (const float*)d_in[1];
    const float* Whh1 = (const float*)d_in[2];
    const float* bih1 = (const float*)d_in[3];
    const float* bhh1 = (const float*)d_in[4];
    const float* Wih2 = (const float*)d_in[5];
    const float* Whh2 = (const float*)d_in[6];
    const float* bih2 = (const float*)d_in[7];
    const float* bhh2 = (const float*)d_in[8];
    const float* Wout = (const float*)d_in[9];
    const float* bout = (const float*)d_in[10];
    float* out = (float*)d_out;

    cudaFuncSetAttribute(lstm_persistent,
                         cudaFuncAttributeMaxDynamicSharedMemorySize, SMEM_BYTES);

    lstm_persistent<<<NCTA, NTH, SMEM_BYTES>>>(x, Wih1, Whh1, bih1, bhh1,
                                               Wih2, Whh2, bih2, bhh2,
                                               Wout, bout, out);
}

// round 5
// speedup vs baseline: 2.9764x; 1.3597x over previous
#include <cuda_runtime.h>
#include <cuda_fp16.h>

#define HID     1024
#define TSTEPS  4096
#define NCTA    128
#define NTH     512   // 16 warps; warp w owns gate-rows {2w,2w+1} of layer1 AND layer2

// SMEM: Whh1/Wih2/Whh2 fp16 (3*64KB) + Wih1 (4KB) + sH1f/sH2f fp32 (2*4KB) + gates (256B)
#define SMEM_BYTES (3*65536 + 4096 + 2*4096 + 256)

// tagged h words: (tag << 32) | fp32 bits. tag = interval+2 (1..4097)
__device__ __align__(16) unsigned long long g_h1q[2][HID];
__device__ __align__(16) unsigned long long g_h2q[2][HID];
__device__ unsigned g_cnt = 0;
__device__ unsigned g_gen = 0;

__device__ __forceinline__ float warpsum(float v) {
#pragma unroll
    for (int s = 16; s; s >>= 1) v += __shfl_xor_sync(0xffffffffu, v, s);
    return v;
}

__device__ __forceinline__ void gridbar() {   // used ONCE, after init
    __syncthreads();
    if (threadIdx.x == 0) {
        __threadfence();
        unsigned g = *((volatile unsigned*)&g_gen);
        if (atomicAdd(&g_cnt, 1u) == NCTA - 1) {
            atomicExch(&g_cnt, 0u);
            __threadfence();
            atomicExch(&g_gen, g + 1u);
        } else {
            while (*((volatile unsigned*)&g_gen) == g) { }
        }
    }
    __syncthreads();
}

__device__ __forceinline__ float sigf(float x) {
    return __fdividef(1.0f, 1.0f + __expf(-x));
}
__device__ __forceinline__ float tanhfast(float x) {
    return 2.0f * __fdividef(1.0f, 1.0f + __expf(-2.0f * x)) - 1.0f;
}

__device__ __forceinline__ void unp8(uint4 u, float* f) {
    float2 t;
    t = __half22float2(*reinterpret_cast<__half2*>(&u.x)); f[0] = t.x; f[1] = t.y;
    t = __half22float2(*reinterpret_cast<__half2*>(&u.y)); f[2] = t.x; f[3] = t.y;
    t = __half22float2(*reinterpret_cast<__half2*>(&u.z)); f[4] = t.x; f[5] = t.y;
    t = __half22float2(*reinterpret_cast<__half2*>(&u.w)); f[6] = t.x; f[7] = t.y;
}

__device__ __forceinline__ void ldcg2q(const unsigned long long* p,
                                       unsigned long long& a, unsigned long long& b) {
    asm volatile("ld.global.cg.v2.u64 {%0,%1}, [%2];"
                 : "=l"(a), "=l"(b) : "l"(p));
}

// poll own 2+2 words of h1/h2 until tags match, then stage fp32 pair into smem
__device__ __forceinline__ void poll_stage(const unsigned long long* p1w,
                                           const unsigned long long* p2w,
                                           unsigned tg, float* sH1f, float* sH2f,
                                           int tid) {
    unsigned long long a0, a1, b0, b1;
    bool oka = false, okb = false;
    do {
        if (!oka) { ldcg2q(p1w, a0, a1);
                    oka = ((unsigned)(a0 >> 32) == tg) & ((unsigned)(a1 >> 32) == tg); }
        if (!okb) { ldcg2q(p2w, b0, b1);
                    okb = ((unsigned)(b0 >> 32) == tg) & ((unsigned)(b1 >> 32) == tg); }
    } while (!(oka && okb));
    ((float2*)sH1f)[tid] = make_float2(__uint_as_float((unsigned)a0),
                                       __uint_as_float((unsigned)a1));
    ((float2*)sH2f)[tid] = make_float2(__uint_as_float((unsigned)b0),
                                       __uint_as_float((unsigned)b1));
}

__device__ __forceinline__ void ld8f(const float* s, int k, float* f) {
    float4 a = ((const float4*)s)[2 * k];
    float4 b = ((const float4*)s)[2 * k + 1];
    f[0] = a.x; f[1] = a.y; f[2] = a.z; f[3] = a.w;
    f[4] = b.x; f[5] = b.y; f[6] = b.z; f[7] = b.w;
}

__global__ void __launch_bounds__(NTH, 1)
lstm_persistent(const float* __restrict__ x,
                const float* __restrict__ Wih1, const float* __restrict__ Whh1,
                const float* __restrict__ bih1, const float* __restrict__ bhh1,
                const float* __restrict__ Wih2, const float* __restrict__ Whh2,
                const float* __restrict__ bih2, const float* __restrict__ bhh2,
                const float* __restrict__ Wout, const float* __restrict__ bout,
                float* __restrict__ out)
{
    extern __shared__ unsigned char sm[];
    __half* sWhh1 = (__half*)sm;                 // [32][1024]
    __half* sWih2 = sWhh1 + 32 * HID;
    __half* sWhh2 = sWih2 + 32 * HID;
    __half* sWih1 = sWhh2 + 32 * HID;            // [32][64]
    float*  sH1f  = (float*)(sWih1 + 32 * 64);   // h1(t)   fp32
    float*  sH2f  = sH1f + HID;                  // h2(t-1) fp32
    float*  sG1   = sH2f + HID;                  // 32 gate-row sums, layer1
    float*  sG2   = sG1 + 32;                    // 32 gate-row sums, layer2

    const int tid  = threadIdx.x;
    const int w    = tid >> 5;
    const int lane = tid & 31;
    const int b    = blockIdx.x;
    const int r0   = 2 * w;
    const int r1   = 2 * w + 1;

    // ---- preload: 3 big mats -> fp16 SMEM ----
    {
        const float* srcs[3] = { Whh1, Wih2, Whh2 };
        __half* dsts[3] = { sWhh1, sWih2, sWhh2 };
        for (int rr = w; rr < 96; rr += 16) {
            int m = rr >> 5, r = rr & 31;
            int g = r & 3, jg = 8 * b + (r >> 2);
            const float4* src = (const float4*)(srcs[m] + ((size_t)g * HID + jg) * HID);
            uint4* dst = (uint4*)(dsts[m] + r * HID);
#pragma unroll
            for (int i = 0; i < 4; ++i) {
                int k = lane + 32 * i;
                float4 a  = __ldg(src + 2 * k);
                float4 bb = __ldg(src + 2 * k + 1);
                uint4 u;
                ((__half2*)&u)[0] = __floats2half2_rn(a.x, a.y);
                ((__half2*)&u)[1] = __floats2half2_rn(a.z, a.w);
                ((__half2*)&u)[2] = __floats2half2_rn(bb.x, bb.y);
                ((__half2*)&u)[3] = __floats2half2_rn(bb.z, bb.w);
                dst[k] = u;
            }
        }
    }
    // ---- preload Wih1 rows r0,r1 ----
#pragma unroll
    for (int rl = 0; rl < 2; ++rl) {
        int r = 2 * w + rl;
        int g = r & 3, jg = 8 * b + (r >> 2);
        if (lane < 16) {
            float4 v = __ldg((const float4*)(Wih1 + ((size_t)g * HID + jg) * 64) + lane);
            __half2* d = (__half2*)(sWih1 + r * 64) + 2 * lane;
            d[0] = __floats2half2_rn(v.x, v.y);
            d[1] = __floats2half2_rn(v.z, v.w);
        }
    }

    // ---- clear stale tags (both parities), then seed h2(-1)=0 with tag 1 ----
    if (tid < 8) {
        int jg = 8 * b + tid;
        __stcg(&g_h1q[0][jg], 0ull);
        __stcg(&g_h1q[1][jg], 0ull);
        __stcg(&g_h2q[0][jg], 0ull);
        __stcg(&g_h2q[1][jg], (1ull << 32));   // tag 1, value fp32(0)
    }

    // ---- finisher role: lane0 of warp w finishes (layer fl, hidden fj) ----
    const int fl = w >> 3, fj = w & 7, fjg = 8 * b + fj;
    float bsum[4] = {0.f, 0.f, 0.f, 0.f};
    if (lane == 0) {
        const float* bi = fl ? bih2 : bih1;
        const float* bh = fl ? bhh2 : bhh1;
#pragma unroll
        for (int g = 0; g < 4; ++g)
            bsum[g] = __ldg(bi + g * HID + fjg) + __ldg(bh + g * HID + fjg);
    }
    float cstate = 0.0f;

    // ---- output-projection role (warp 15 of CTA 1 -> col0, CTA 65 -> col1) ----
    const bool outcta = (b == 1 || b == 65);
    const bool outw = (w == 15) && outcta;
    const int  oi   = (b == 65) ? 1 : 0;
    float bo = 0.0f;
    if (outw && lane == 0) bo = __ldg(bout + oi);
    const float4* worow = (const float4*)(Wout + oi * HID);

    gridbar();   // stale tags cleared everywhere before anyone publishes/polls

    // ---- prologue: h1(0) = gates(Wih1 @ x(0) + biases); publish tag 1 ----
    {
        float2 xv = __ldg((const float2*)x + lane);
        float2 w0 = __half22float2(((const __half2*)(sWih1 + r0 * 64))[lane]);
        float2 w1 = __half22float2(((const __half2*)(sWih1 + r1 * 64))[lane]);
        float a0 = warpsum(fmaf(w0.x, xv.x, w0.y * xv.y));
        float a1 = warpsum(fmaf(w1.x, xv.x, w1.y * xv.y));
        if (lane == 0) { sG1[r0] = a0; sG1[r1] = a1; }
        __syncthreads();
        if (lane == 0 && fl == 0) {
            float gi = sG1[fj * 4 + 0] + bsum[0];
            float gg = sG1[fj * 4 + 2] + bsum[2];
            float go = sG1[fj * 4 + 3] + bsum[3];
            cstate = sigf(gi) * tanhfast(gg);
            float h = sigf(go) * tanhfast(cstate);
            unsigned long long word = (1ull << 32)
                                    | (unsigned long long)__float_as_uint(h);
            __stcg(&g_h1q[0][fjg], word);
        }
    }

    // poll pointers per parity (this thread's 2 words of each array)
    const unsigned long long* h1p[2] = { &g_h1q[0][2 * tid], &g_h1q[1][2 * tid] };
    const unsigned long long* h2p[2] = { &g_h2q[0][2 * tid], &g_h2q[1][2 * tid] };

    // ==== main loop: interval t consumes h1(t),h2(t-1); publishes h2(t),h1(t+1) ====
    for (int t = 0; t < TSTEPS; ++t) {
        const int p1 = t & 1;
        const int p2 = p1 ^ 1;
        const unsigned tg = (unsigned)(t + 1);

        // ---- data-carrying barrier: poll + stage in one pass ----
        poll_stage(h1p[p1], h2p[p2], tg, sH1f, sH2f, tid);
        __syncthreads();

        // out[t-1] = Wout @ h2(t-1)
        if (outw && t > 0) {
            float a = 0.f;
#pragma unroll
            for (int c = 0; c < 4; ++c) {
                int k = lane + 32 * c;
                float hf[8]; ld8f(sH2f, k, hf);
                float4 wa = __ldg(worow + 2 * k);
                float4 wb = __ldg(worow + 2 * k + 1);
                a = fmaf(wa.x, hf[0], fmaf(wa.y, hf[1], fmaf(wa.z, hf[2], fmaf(wa.w, hf[3], a))));
                a = fmaf(wb.x, hf[4], fmaf(wb.y, hf[5], fmaf(wb.z, hf[6], fmaf(wb.w, hf[7], a))));
            }
            a = warpsum(a);
            if (lane == 0) out[(t - 1) * 2 + oi] = a + bo;
        }

        // ---- dots: a1* = Whh1@h1(t) rows r0,r1 ; a2* = Wih2@h1(t)+Whh2@h2(t-1) ----
        float a1x = 0.f, a1y = 0.f, a2x = 0.f, a2y = 0.f;
        const uint4* W11a = (const uint4*)(sWhh1 + r0 * HID);
        const uint4* W11b = (const uint4*)(sWhh1 + r1 * HID);
        const uint4* Wi2a = (const uint4*)(sWih2 + r0 * HID);
        const uint4* Wi2b = (const uint4*)(sWih2 + r1 * HID);
        const uint4* Wh2a = (const uint4*)(sWhh2 + r0 * HID);
        const uint4* Wh2b = (const uint4*)(sWhh2 + r1 * HID);
#pragma unroll
        for (int c = 0; c < 4; ++c) {
            int k = lane + 32 * c;
            float h1f[8], h2f[8], wf[8];
            ld8f(sH1f, k, h1f);
            ld8f(sH2f, k, h2f);
            unp8(W11a[k], wf);
#pragma unroll
            for (int e = 0; e < 8; ++e) a1x = fmaf(wf[e], h1f[e], a1x);
            unp8(W11b[k], wf);
#pragma unroll
            for (int e = 0; e < 8; ++e) a1y = fmaf(wf[e], h1f[e], a1y);
            unp8(Wi2a[k], wf);
#pragma unroll
            for (int e = 0; e < 8; ++e) a2x = fmaf(wf[e], h1f[e], a2x);
            unp8(Wi2b[k], wf);
#pragma unroll
            for (int e = 0; e < 8; ++e) a2y = fmaf(wf[e], h1f[e], a2y);
            unp8(Wh2a[k], wf);
#pragma unroll
            for (int e = 0; e < 8; ++e) a2x = fmaf(wf[e], h2f[e], a2x);
            unp8(Wh2b[k], wf);
#pragma unroll
            for (int e = 0; e < 8; ++e) a2y = fmaf(wf[e], h2f[e], a2y);
        }
        // + Wih1 @ x(t+1) into layer-1 rows
        {
            float2 xv = make_float2(0.f, 0.f);
            if (t + 1 < TSTEPS)
                xv = __ldg((const float2*)(x + (size_t)(t + 1) * 64) + lane);
            float2 w0 = __half22float2(((const __half2*)(sWih1 + r0 * 64))[lane]);
            float2 w1 = __half22float2(((const __half2*)(sWih1 + r1 * 64))[lane]);
            a1x = fmaf(w0.x, xv.x, fmaf(w0.y, xv.y, a1x));
            a1y = fmaf(w1.x, xv.x, fmaf(w1.y, xv.y, a1y));
        }

        a1x = warpsum(a1x); a1y = warpsum(a1y);
        a2x = warpsum(a2x); a2y = warpsum(a2y);
        if (lane == 0) { sG1[r0] = a1x; sG1[r1] = a1y; sG2[r0] = a2x; sG2[r1] = a2y; }
        __syncthreads();

        // ---- finish: lane0 of warp w updates (fl,fj), publishes tagged word ----
        if (lane == 0) {
            const float* sG = fl ? sG2 : sG1;
            float gi = sG[fj * 4 + 0] + bsum[0];
            float gf = sG[fj * 4 + 1] + bsum[1];
            float gg = sG[fj * 4 + 2] + bsum[2];
            float go = sG[fj * 4 + 3] + bsum[3];
            cstate = sigf(gf) * cstate + sigf(gi) * tanhfast(gg);
            float h = sigf(go) * tanhfast(cstate);
            unsigned long long word = ((unsigned long long)(t + 2) << 32)
                                    | (unsigned long long)__float_as_uint(h);
            if (fl == 0) __stcg(&g_h1q[p2][fjg], word);   // h1(t+1)
            else         __stcg(&g_h2q[p1][fjg], word);   // h2(t)
        }
        // no end-of-loop barrier: next interval's poll gates on all publishes
    }

    // ---- epilogue: out[T-1] from h2(T-1) (tag 4097, parity 1) ----
    if (outcta) {
        {
            unsigned long long b0v, b1v;
            const unsigned tg = (unsigned)(TSTEPS + 1);
            bool ok = false;
            do { ldcg2q(h2p[1], b0v, b1v);
                 ok = ((unsigned)(b0v >> 32) == tg) & ((unsigned)(b1v >> 32) == tg);
            } while (!ok);
            ((float2*)sH2f)[tid] = make_float2(__uint_as_float((unsigned)b0v),
                                               __uint_as_float((unsigned)b1v));
        }
        __syncthreads();
        if (outw) {
            float a = 0.f;
#pragma unroll
            for (int c = 0; c < 4; ++c) {
                int k = lane + 32 * c;
                float hf[8]; ld8f(sH2f, k, hf);
                float4 wa = __ldg(worow + 2 * k);
                float4 wb = __ldg(worow + 2 * k + 1);
                a = fmaf(wa.x, hf[0], fmaf(wa.y, hf[1], fmaf(wa.z, hf[2], fmaf(wa.w, hf[3], a))));
                a = fmaf(wb.x, hf[4], fmaf(wb.y, hf[5], fmaf(wb.z, hf[6], fmaf(wb.w, hf[7], a))));
            }
            a = warpsum(a);
            if (lane == 0) out[(TSTEPS - 1) * 2 + oi] = a + bo;
        }
    }
}

extern "C" void kernel_launch(void* const* d_in, const int* in_sizes, int n_in,
                              void* d_out, int out_size)
{
    const float* x    = (const float*)d_in[0];
    const float* Wih1 = (const float*)d_in[1];
    const float* Whh1 = (const float*)d_in[2];
    const float* bih1 = (const float*)d_in[3];
    const float* bhh1 = (const float*)d_in[4];
    const float* Wih2 = (const float*)d_in[5];
    const float* Whh2 = (const float*)d_in[6];
    const float* bih2 = (const float*)d_in[7];
    const float* bhh2 = (const float*)d_in[8];
    const float* Wout = (const float*)d_in[9];
    const float* bout = (const float*)d_in[10];
    float* out = (float*)d_out;

    cudaFuncSetAttribute(lstm_persistent,
                         cudaFuncAttributeMaxDynamicSharedMemorySize, SMEM_BYTES);

    lstm_persistent<<<NCTA, NTH, SMEM_BYTES>>>(x, Wih1, Whh1, bih1, bhh1,
                                               Wih2, Whh2, bih2, bhh2,
                                               Wout, bout, out);
}